// round 15
// baseline (speedup 1.0000x reference)
#include <cuda_runtime.h>
#include <cuda_fp16.h>
#include <math.h>
#include <stdint.h>

#define N_NODES 10000
#define N_EDGES 320000
#define H2 256          // node feature width
#define H4 512          // concat width
#define ELLW 128        // padded adjacency width

// Scratch (static __device__ arrays -- no allocation allowed)
__device__ int    g_ell[(size_t)N_NODES * ELLW];
__device__ int    g_cur[N_NODES];
__device__ __half g_xh[(size_t)N_NODES * H2];    // fp16 copy of x
__device__ __half g_cath[(size_t)N_NODES * H4];  // fp16 cat = [x, deg*x - S]
__device__ __half g_hh[(size_t)N_NODES * H2];    // fp16 GEMM1 output
__device__ __half g_w1t[(size_t)H2 * H4];        // W1^T fp16 [N=256][K=512]
__device__ __half g_w2t[(size_t)H2 * H2];        // W2^T fp16 [N=256][K=256]

// ---------------------------------------------------------------------------
// Prep: zero cursors, fp16 x copy, fp16 transposed weights. One launch.
// ---------------------------------------------------------------------------
__global__ void prep_kernel(const float* __restrict__ x,
                            const float* __restrict__ W1,
                            const float* __restrict__ W2) {
    int i = blockIdx.x * blockDim.x + threadIdx.x;
    if (i < N_NODES) g_cur[i] = 0;
    if (i < N_NODES * H2) g_xh[i] = __float2half_rn(x[i]);
    if (i < H4 * H2) {                      // W1 [512][256] -> w1t [256][512]
        int k = i >> 8, n = i & 255;
        g_w1t[(size_t)n * H4 + k] = __float2half_rn(W1[i]);
    }
    if (i < H2 * H2) {                      // W2 [256][256] -> w2t [256][256]
        int k = i >> 8, n = i & 255;
        g_w2t[(size_t)n * H2 + k] = __float2half_rn(W2[i]);
    }
}

__global__ void fill_ell_kernel(const int* __restrict__ esrc,
                                const int* __restrict__ edst) {
    int e = blockIdx.x * blockDim.x + threadIdx.x;
    if (e >= N_EDGES) return;
    int s = esrc[e];
    int d = edst[e];
    int pos = atomicAdd(&g_cur[d], 1);
    if (pos < ELLW) g_ell[((size_t)d << 7) + pos] = s;
}

// ---------------------------------------------------------------------------
// Gather + cat (fp16 in / fp16 out). One warp per node.
// ---------------------------------------------------------------------------
union H8 { uint4 u; __half2 h[4]; };

__device__ __forceinline__ void acc8(float* a, uint4 v) {
    H8 p; p.u = v;
#pragma unroll
    for (int t = 0; t < 4; ++t) {
        float2 f = __half22float2(p.h[t]);
        a[2 * t]     += f.x;
        a[2 * t + 1] += f.y;
    }
}

__global__ __launch_bounds__(256)
void gather_cat_kernel(const float* __restrict__ x) {
    int gtid = blockIdx.x * blockDim.x + threadIdx.x;
    int node = gtid >> 5;
    int lane = gtid & 31;
    if (node >= N_NODES) return;

    int deg = g_cur[node];
    const int* __restrict__ nbr = g_ell + ((size_t)node << 7);
    const uint4* __restrict__ xh4 = (const uint4*)g_xh;   // 32 chunks/row

    float a[8];
#pragma unroll
    for (int i = 0; i < 8; ++i) a[i] = 0.f;

    int j = 0;
    for (; j + 4 <= deg; j += 4) {
        int s0 = nbr[j], s1 = nbr[j + 1], s2 = nbr[j + 2], s3 = nbr[j + 3];
        uint4 v0 = xh4[(size_t)s0 * 32 + lane];
        uint4 v1 = xh4[(size_t)s1 * 32 + lane];
        uint4 v2 = xh4[(size_t)s2 * 32 + lane];
        uint4 v3 = xh4[(size_t)s3 * 32 + lane];
        acc8(a, v0); acc8(a, v1); acc8(a, v2); acc8(a, v3);
    }
    for (; j < deg; ++j) {
        uint4 v = xh4[(size_t)nbr[j] * 32 + lane];
        acc8(a, v);
    }

    const float4* x4 = (const float4*)x;
    float4 xa = x4[(size_t)node * 64 + 2 * lane];
    float4 xb = x4[(size_t)node * 64 + 2 * lane + 1];
    float dg = (float)deg;

    H8 xo, po;
    xo.h[0] = __floats2half2_rn(xa.x, xa.y);
    xo.h[1] = __floats2half2_rn(xa.z, xa.w);
    xo.h[2] = __floats2half2_rn(xb.x, xb.y);
    xo.h[3] = __floats2half2_rn(xb.z, xb.w);
    po.h[0] = __floats2half2_rn(dg * xa.x - a[0], dg * xa.y - a[1]);
    po.h[1] = __floats2half2_rn(dg * xa.z - a[2], dg * xa.w - a[3]);
    po.h[2] = __floats2half2_rn(dg * xb.x - a[4], dg * xb.y - a[5]);
    po.h[3] = __floats2half2_rn(dg * xb.z - a[6], dg * xb.w - a[7]);

    uint4* cat16 = (uint4*)g_cath;          // 64 chunks/row
    cat16[(size_t)node * 64 + lane]      = xo.u;
    cat16[(size_t)node * 64 + 32 + lane] = po.u;
}

// ---------------------------------------------------------------------------
// fp16 mma.sync GEMM (m16n8k16, fp32 acc) + ldmatrix + 3-stage cp.async.
//   C[M,N] = A[M,K] @ Bt[N,K]^T + bias
// Block tile 64x64x64, 256 threads (8 warps 4x2), warp tile 16x32.
// A/Bt smem [row][k], LDK=72 halves (144 B rows): ldmatrix row addresses
// advance 16 B mod 128 -> conflict-free. 32 warps/SM at 4 CTAs/SM.
// EPI: 0 = fp16 store (GEMM1), 1 = tanh + fp32 store (GEMM2)
// ---------------------------------------------------------------------------
__device__ __forceinline__ void cp16(uint32_t dst, const void* src, int srcsz) {
    asm volatile("cp.async.cg.shared.global [%0], [%1], 16, %2;"
                 :: "r"(dst), "l"(src), "r"(srcsz) : "memory");
}
#define CP_COMMIT() asm volatile("cp.async.commit_group;" ::: "memory")
#define CP_WAIT(n)  asm volatile("cp.async.wait_group %0;" :: "n"(n) : "memory")

#define LDSM_X4(r0, r1, r2, r3, addr) \
    asm volatile("ldmatrix.sync.aligned.m8n8.x4.shared.b16 {%0,%1,%2,%3}, [%4];" \
                 : "=r"(r0), "=r"(r1), "=r"(r2), "=r"(r3) : "r"(addr))

#define BM 64
#define BN 64
#define BK 64                         // k halves per stage
#define LDK 72                        // smem row halves (144 B)
#define A_ST (BM * LDK)               // 4608 halves / stage (9216 B)
#define NSTAGE 3
#define SMEM_BYTES (2 * NSTAGE * A_ST * 2)   // A+B, 3 stages: 55296 B

template<int EPI>
__global__ __launch_bounds__(256, 4)
void mma_gemm(const __half* __restrict__ A, const __half* __restrict__ Bt,
              const float* __restrict__ bias, void* __restrict__ Cout,
              int M, int N, int K)
{
    extern __shared__ __half smh[];
    __half* Asm = smh;                       // [NSTAGE][A_ST]
    __half* Bsm = smh + NSTAGE * A_ST;       // [NSTAGE][A_ST]
    uint32_t a_sa = (uint32_t)__cvta_generic_to_shared(Asm);
    uint32_t b_sa = (uint32_t)__cvta_generic_to_shared(Bsm);

    const int tid  = threadIdx.x;
    const int wid  = tid >> 5;
    const int lane = tid & 31;
    const int r = lane >> 2;
    const int c = lane & 3;
    const int wm0 = (wid & 3) * 16;       // 4 warps over M
    const int wn0 = (wid >> 2) * 32;      // 2 warps over N
    const int m0 = blockIdx.x * BM, n0 = blockIdx.y * BN;

    // ldmatrix lane addressing (within-tile, halves)
    const int a_row = wm0 + (lane & 15);
    const int a_ksl = (lane >> 4) * 8;
    const int b_row = wn0 + (lane & 7) + ((lane >> 4) << 3);
    const int b_ksl = ((lane >> 3) & 1) * 8;

    float acc[4][4];                      // [nt][quad]
#pragma unroll
    for (int j = 0; j < 4; ++j)
#pragma unroll
        for (int q = 0; q < 4; ++q) acc[j][q] = 0.f;

    const int T = K / BK;

    // cp.async per stage: A 64 rows x 8 chunks = 512 (2/thread), B same.
    auto prefetch = [&](int t, int buf) {
        uint32_t ab = a_sa + (uint32_t)buf * A_ST * 2;
        uint32_t bb = b_sa + (uint32_t)buf * A_ST * 2;
        const __half* Ap = A + (size_t)t * BK;
        const __half* Bp = Bt + (size_t)t * BK;
#pragma unroll
        for (int i = 0; i < 2; ++i) {
            int ch  = tid + 256 * i;
            int row = ch >> 3, seg = ch & 7;
            int gm  = m0 + row;
            cp16(ab + row * (LDK * 2) + seg * 16,
                 Ap + (size_t)gm * K + seg * 8, gm < M ? 16 : 0);
            cp16(bb + row * (LDK * 2) + seg * 16,
                 Bp + (size_t)(n0 + row) * K + seg * 8, 16);
        }
        CP_COMMIT();
    };

    prefetch(0, 0);
    if (T > 1) prefetch(1, 1);

    for (int t = 0; t < T; ++t) {
        int buf = t % NSTAGE;
        if (t + 2 < T) {
            prefetch(t + 2, (t + 2) % NSTAGE);
            CP_WAIT(2);
        } else if (t + 1 < T) {
            CP_WAIT(1);
        } else {
            CP_WAIT(0);
        }
        __syncthreads();

        uint32_t ab = a_sa + (uint32_t)buf * A_ST * 2;
        uint32_t bb = b_sa + (uint32_t)buf * A_ST * 2;

#pragma unroll
        for (int kt = 0; kt < 4; ++kt) {
            int kb = kt * 16;
            unsigned af[4], bf[2][4];
            LDSM_X4(af[0], af[1], af[2], af[3],
                    ab + (uint32_t)(a_row * LDK + kb + a_ksl) * 2);
            LDSM_X4(bf[0][0], bf[0][1], bf[0][2], bf[0][3],
                    bb + (uint32_t)(b_row * LDK + kb + b_ksl) * 2);
            LDSM_X4(bf[1][0], bf[1][1], bf[1][2], bf[1][3],
                    bb + (uint32_t)((b_row + 16) * LDK + kb + b_ksl) * 2);
#pragma unroll
            for (int nt = 0; nt < 4; ++nt) {
                unsigned b0 = bf[nt >> 1][(nt & 1) * 2];
                unsigned b1 = bf[nt >> 1][(nt & 1) * 2 + 1];
                asm volatile(
                    "mma.sync.aligned.m16n8k16.row.col.f32.f16.f16.f32 "
                    "{%0,%1,%2,%3}, {%4,%5,%6,%7}, {%8,%9}, {%0,%1,%2,%3};"
                    : "+f"(acc[nt][0]), "+f"(acc[nt][1]),
                      "+f"(acc[nt][2]), "+f"(acc[nt][3])
                    : "r"(af[0]), "r"(af[1]), "r"(af[2]), "r"(af[3]),
                      "r"(b0), "r"(b1));
            }
        }
        __syncthreads();
    }

    // Epilogue: c0,c1 -> row r cols 2c,2c+1; c2,c3 -> row r+8.
#pragma unroll
    for (int half = 0; half < 2; ++half) {
        int gm = m0 + wm0 + r + half * 8;
        if (gm >= M) continue;
#pragma unroll
        for (int nt = 0; nt < 4; ++nt) {
            int gn = n0 + wn0 + nt * 8 + 2 * c;
            float v0 = acc[nt][half * 2 + 0] + bias[gn];
            float v1 = acc[nt][half * 2 + 1] + bias[gn + 1];
            if (EPI == 0) {
                *(__half2*)((__half*)Cout + (size_t)gm * N + gn) =
                    __floats2half2_rn(v0, v1);
            } else {
                *(float2*)((float*)Cout + (size_t)gm * N + gn) =
                    make_float2(tanhf(v0), tanhf(v1));
            }
        }
    }
}

// ---------------------------------------------------------------------------
extern "C" void kernel_launch(void* const* d_in, const int* in_sizes, int n_in,
                              void* d_out, int out_size) {
    const float* x    = (const float*)d_in[0];   // node_feats [10000,256]
    const float* W1   = (const float*)d_in[1];   // [512,256]
    const float* b1   = (const float*)d_in[2];   // [256]
    const float* W2   = (const float*)d_in[3];   // [256,256]
    const float* b2   = (const float*)d_in[4];   // [256]
    const int*   esrc = (const int*)d_in[5];     // [320000]
    const int*   edst = (const int*)d_in[6];     // [320000]
    float*       out  = (float*)d_out;           // [10000,256]

    void *cat_p = nullptr, *h_p = nullptr, *w1_p = nullptr, *w2_p = nullptr;
    cudaGetSymbolAddress(&cat_p, g_cath);
    cudaGetSymbolAddress(&h_p, g_hh);
    cudaGetSymbolAddress(&w1_p, g_w1t);
    cudaGetSymbolAddress(&w2_p, g_w2t);
    const __half* cath = (const __half*)cat_p;
    __half*       hh   = (__half*)h_p;
    const __half* w1t  = (const __half*)w1_p;
    const __half* w2t  = (const __half*)w2_p;

    static bool attr_set = false;
    if (!attr_set) {
        cudaFuncSetAttribute(mma_gemm<0>,
                             cudaFuncAttributeMaxDynamicSharedMemorySize, SMEM_BYTES);
        cudaFuncSetAttribute(mma_gemm<1>,
                             cudaFuncAttributeMaxDynamicSharedMemorySize, SMEM_BYTES);
        attr_set = true;
    }

    // 1) prep: zero cursors, fp16 x, fp16 transposed weights
    prep_kernel<<<(N_NODES * H2 + 255) / 256, 256>>>(x, W1, W2);
    // 2) build padded adjacency
    fill_ell_kernel<<<(N_EDGES + 255) / 256, 256>>>(esrc, edst);
    // 3) gather + cat (fp16 gather, fp16 cat)
    gather_cat_kernel<<<(N_NODES * 32 + 255) / 256, 256>>>(x);
    // 4) h = cat @ W1 + b1  (fp16 mma + ldmatrix, 256 threads, 8 warps)
    {
        dim3 grid((N_NODES + BM - 1) / BM, H2 / BN);
        mma_gemm<0><<<grid, 256, SMEM_BYTES>>>(cath, w1t, b1, hh, N_NODES, H2, H4);
    }
    // 5) out = tanh(h @ W2 + b2)
    {
        dim3 grid((N_NODES + BM - 1) / BM, H2 / BN);
        mma_gemm<1><<<grid, 256, SMEM_BYTES>>>(hh, w2t, b2, out, N_NODES, H2, H2);
    }
}

// round 16
// speedup vs baseline: 1.1138x; 1.1138x over previous
#include <cuda_runtime.h>
#include <cuda_fp16.h>
#include <math.h>
#include <stdint.h>

#define N_NODES 10000
#define N_EDGES 320000
#define H2 256          // node feature width
#define H4 512          // concat width
#define ELLW 128        // padded adjacency width

// Scratch (static __device__ arrays -- no allocation allowed)
__device__ int    g_ell[(size_t)N_NODES * ELLW];
__device__ int    g_cur[N_NODES];
__device__ __half g_xh[(size_t)N_NODES * H2];    // fp16 copy of x
__device__ __half g_cath[(size_t)N_NODES * H4];  // fp16 cat = [x, deg*x - S]
__device__ __half g_hh[(size_t)N_NODES * H2];    // fp16 GEMM1 output
__device__ __half g_w1t[(size_t)H2 * H4];        // W1^T fp16 [N=256][K=512]
__device__ __half g_w2t[(size_t)H2 * H2];        // W2^T fp16 [N=256][K=256]

// ---------------------------------------------------------------------------
// Prep: zero cursors, fp16 x copy, fp16 transposed weights. One launch.
// ---------------------------------------------------------------------------
__global__ void prep_kernel(const float* __restrict__ x,
                            const float* __restrict__ W1,
                            const float* __restrict__ W2) {
    int i = blockIdx.x * blockDim.x + threadIdx.x;
    if (i < N_NODES) g_cur[i] = 0;
    if (i < N_NODES * H2) g_xh[i] = __float2half_rn(x[i]);
    if (i < H4 * H2) {                      // W1 [512][256] -> w1t [256][512]
        int k = i >> 8, n = i & 255;
        g_w1t[(size_t)n * H4 + k] = __float2half_rn(W1[i]);
    }
    if (i < H2 * H2) {                      // W2 [256][256] -> w2t [256][256]
        int k = i >> 8, n = i & 255;
        g_w2t[(size_t)n * H2 + k] = __float2half_rn(W2[i]);
    }
}

__global__ void fill_ell_kernel(const int* __restrict__ esrc,
                                const int* __restrict__ edst) {
    int e = blockIdx.x * blockDim.x + threadIdx.x;
    if (e >= N_EDGES) return;
    int s = esrc[e];
    int d = edst[e];
    int pos = atomicAdd(&g_cur[d], 1);
    if (pos < ELLW) g_ell[((size_t)d << 7) + pos] = s;
}

// ---------------------------------------------------------------------------
// Gather + cat (fp16 in / fp16 out). One warp per node.
// ---------------------------------------------------------------------------
union H8 { uint4 u; __half2 h[4]; };

__device__ __forceinline__ void acc8(float* a, uint4 v) {
    H8 p; p.u = v;
#pragma unroll
    for (int t = 0; t < 4; ++t) {
        float2 f = __half22float2(p.h[t]);
        a[2 * t]     += f.x;
        a[2 * t + 1] += f.y;
    }
}

__global__ __launch_bounds__(256)
void gather_cat_kernel(const float* __restrict__ x) {
    int gtid = blockIdx.x * blockDim.x + threadIdx.x;
    int node = gtid >> 5;
    int lane = gtid & 31;
    if (node >= N_NODES) return;

    int deg = g_cur[node];
    const int* __restrict__ nbr = g_ell + ((size_t)node << 7);
    const uint4* __restrict__ xh4 = (const uint4*)g_xh;   // 32 chunks/row

    float a[8];
#pragma unroll
    for (int i = 0; i < 8; ++i) a[i] = 0.f;

    int j = 0;
    for (; j + 4 <= deg; j += 4) {
        int s0 = nbr[j], s1 = nbr[j + 1], s2 = nbr[j + 2], s3 = nbr[j + 3];
        uint4 v0 = xh4[(size_t)s0 * 32 + lane];
        uint4 v1 = xh4[(size_t)s1 * 32 + lane];
        uint4 v2 = xh4[(size_t)s2 * 32 + lane];
        uint4 v3 = xh4[(size_t)s3 * 32 + lane];
        acc8(a, v0); acc8(a, v1); acc8(a, v2); acc8(a, v3);
    }
    for (; j < deg; ++j) {
        uint4 v = xh4[(size_t)nbr[j] * 32 + lane];
        acc8(a, v);
    }

    const float4* x4 = (const float4*)x;
    float4 xa = x4[(size_t)node * 64 + 2 * lane];
    float4 xb = x4[(size_t)node * 64 + 2 * lane + 1];
    float dg = (float)deg;

    H8 xo, po;
    xo.h[0] = __floats2half2_rn(xa.x, xa.y);
    xo.h[1] = __floats2half2_rn(xa.z, xa.w);
    xo.h[2] = __floats2half2_rn(xb.x, xb.y);
    xo.h[3] = __floats2half2_rn(xb.z, xb.w);
    po.h[0] = __floats2half2_rn(dg * xa.x - a[0], dg * xa.y - a[1]);
    po.h[1] = __floats2half2_rn(dg * xa.z - a[2], dg * xa.w - a[3]);
    po.h[2] = __floats2half2_rn(dg * xb.x - a[4], dg * xb.y - a[5]);
    po.h[3] = __floats2half2_rn(dg * xb.z - a[6], dg * xb.w - a[7]);

    uint4* cat16 = (uint4*)g_cath;          // 64 chunks/row
    cat16[(size_t)node * 64 + lane]      = xo.u;
    cat16[(size_t)node * 64 + 32 + lane] = po.u;
}

// ---------------------------------------------------------------------------
// fp16 mma.sync GEMM (m16n8k16, fp32 acc) + ldmatrix + 2-stage cp.async.
//   C[M,N] = A[M,K] @ Bt[N,K]^T + bias
// Block tile 64x64x64, 128 threads (4 warps 2x2), warp tile 32x32.
// A/Bt smem [row][k], LDK=72 halves (144 B rows): conflict-free ldmatrix.
// 2 stages (36.9 KB) + regs<=102 -> 5 CTAs/SM -> single wave for grid=628.
// Per k-tile: 16 LDSM + 64 HMMA per warp between one barrier pair.
// EPI: 0 = fp16 store (GEMM1), 1 = tanh + fp32 store (GEMM2)
// ---------------------------------------------------------------------------
__device__ __forceinline__ void cp16(uint32_t dst, const void* src, int srcsz) {
    asm volatile("cp.async.cg.shared.global [%0], [%1], 16, %2;"
                 :: "r"(dst), "l"(src), "r"(srcsz) : "memory");
}
#define CP_COMMIT() asm volatile("cp.async.commit_group;" ::: "memory")
#define CP_WAIT(n)  asm volatile("cp.async.wait_group %0;" :: "n"(n) : "memory")

#define LDSM_X4(r0, r1, r2, r3, addr) \
    asm volatile("ldmatrix.sync.aligned.m8n8.x4.shared.b16 {%0,%1,%2,%3}, [%4];" \
                 : "=r"(r0), "=r"(r1), "=r"(r2), "=r"(r3) : "r"(addr))

#define BM 64
#define BN 64
#define BK 64                         // k halves per stage
#define LDK 72                        // smem row halves (144 B)
#define A_ST (BM * LDK)               // 4608 halves / stage (9216 B)
#define NSTAGE 2
#define SMEM_BYTES (2 * NSTAGE * A_ST * 2)   // A+B, 2 stages: 36864 B

template<int EPI>
__global__ __launch_bounds__(128, 5)
void mma_gemm(const __half* __restrict__ A, const __half* __restrict__ Bt,
              const float* __restrict__ bias, void* __restrict__ Cout,
              int M, int N, int K)
{
    extern __shared__ __half smh[];
    __half* Asm = smh;                       // [NSTAGE][A_ST]
    __half* Bsm = smh + NSTAGE * A_ST;       // [NSTAGE][A_ST]
    uint32_t a_sa = (uint32_t)__cvta_generic_to_shared(Asm);
    uint32_t b_sa = (uint32_t)__cvta_generic_to_shared(Bsm);

    const int tid  = threadIdx.x;
    const int wid  = tid >> 5;
    const int lane = tid & 31;
    const int r = lane >> 2;
    const int c = lane & 3;
    const int wm0 = (wid & 1) * 32;
    const int wn0 = (wid >> 1) * 32;
    const int m0 = blockIdx.x * BM, n0 = blockIdx.y * BN;

    // ldmatrix lane addressing (within-tile, halves)
    const int a_row = wm0 + (lane & 15);
    const int a_ksl = (lane >> 4) * 8;
    const int b_row = wn0 + (lane & 7) + ((lane >> 4) << 3);
    const int b_ksl = ((lane >> 3) & 1) * 8;

    float acc[2][4][4];
#pragma unroll
    for (int i = 0; i < 2; ++i)
#pragma unroll
        for (int j = 0; j < 4; ++j)
#pragma unroll
            for (int q = 0; q < 4; ++q) acc[i][j][q] = 0.f;

    const int T = K / BK;

    // cp.async per stage: A 64 rows x 8 chunks = 512 (4/thread), B same.
    auto prefetch = [&](int t, int buf) {
        uint32_t ab = a_sa + (uint32_t)buf * A_ST * 2;
        uint32_t bb = b_sa + (uint32_t)buf * A_ST * 2;
        const __half* Ap = A + (size_t)t * BK;
        const __half* Bp = Bt + (size_t)t * BK;
#pragma unroll
        for (int i = 0; i < 4; ++i) {
            int ch  = tid + 128 * i;
            int row = ch >> 3, seg = ch & 7;
            int gm  = m0 + row;
            cp16(ab + row * (LDK * 2) + seg * 16,
                 Ap + (size_t)gm * K + seg * 8, gm < M ? 16 : 0);
            cp16(bb + row * (LDK * 2) + seg * 16,
                 Bp + (size_t)(n0 + row) * K + seg * 8, 16);
        }
        CP_COMMIT();
    };

    prefetch(0, 0);

    for (int t = 0; t < T; ++t) {
        int buf = t & 1;
        if (t + 1 < T) {
            prefetch(t + 1, 1 - buf);
            CP_WAIT(1);
        } else {
            CP_WAIT(0);
        }
        __syncthreads();

        uint32_t ab = a_sa + (uint32_t)buf * A_ST * 2;
        uint32_t bb = b_sa + (uint32_t)buf * A_ST * 2;

#pragma unroll
        for (int kt = 0; kt < 4; ++kt) {
            int kb = kt * 16;
            unsigned af[2][4], bf[2][4];
            LDSM_X4(af[0][0], af[0][1], af[0][2], af[0][3],
                    ab + (uint32_t)(a_row * LDK + kb + a_ksl) * 2);
            LDSM_X4(af[1][0], af[1][1], af[1][2], af[1][3],
                    ab + (uint32_t)((a_row + 16) * LDK + kb + a_ksl) * 2);
            LDSM_X4(bf[0][0], bf[0][1], bf[0][2], bf[0][3],
                    bb + (uint32_t)(b_row * LDK + kb + b_ksl) * 2);
            LDSM_X4(bf[1][0], bf[1][1], bf[1][2], bf[1][3],
                    bb + (uint32_t)((b_row + 16) * LDK + kb + b_ksl) * 2);
#pragma unroll
            for (int nt = 0; nt < 4; ++nt) {
                unsigned b0 = bf[nt >> 1][(nt & 1) * 2];
                unsigned b1 = bf[nt >> 1][(nt & 1) * 2 + 1];
#pragma unroll
                for (int mt = 0; mt < 2; ++mt) {
                    asm volatile(
                        "mma.sync.aligned.m16n8k16.row.col.f32.f16.f16.f32 "
                        "{%0,%1,%2,%3}, {%4,%5,%6,%7}, {%8,%9}, {%0,%1,%2,%3};"
                        : "+f"(acc[mt][nt][0]), "+f"(acc[mt][nt][1]),
                          "+f"(acc[mt][nt][2]), "+f"(acc[mt][nt][3])
                        : "r"(af[mt][0]), "r"(af[mt][1]),
                          "r"(af[mt][2]), "r"(af[mt][3]),
                          "r"(b0), "r"(b1));
                }
            }
        }
        __syncthreads();
    }

    // Epilogue: c0,c1 -> row r cols 2c,2c+1; c2,c3 -> row r+8.
#pragma unroll
    for (int mt = 0; mt < 2; ++mt) {
#pragma unroll
        for (int half = 0; half < 2; ++half) {
            int gm = m0 + wm0 + mt * 16 + r + half * 8;
            if (gm >= M) continue;
#pragma unroll
            for (int nt = 0; nt < 4; ++nt) {
                int gn = n0 + wn0 + nt * 8 + 2 * c;
                float v0 = acc[mt][nt][half * 2 + 0] + bias[gn];
                float v1 = acc[mt][nt][half * 2 + 1] + bias[gn + 1];
                if (EPI == 0) {
                    *(__half2*)((__half*)Cout + (size_t)gm * N + gn) =
                        __floats2half2_rn(v0, v1);
                } else {
                    *(float2*)((float*)Cout + (size_t)gm * N + gn) =
                        make_float2(tanhf(v0), tanhf(v1));
                }
            }
        }
    }
}

// ---------------------------------------------------------------------------
extern "C" void kernel_launch(void* const* d_in, const int* in_sizes, int n_in,
                              void* d_out, int out_size) {
    const float* x    = (const float*)d_in[0];   // node_feats [10000,256]
    const float* W1   = (const float*)d_in[1];   // [512,256]
    const float* b1   = (const float*)d_in[2];   // [256]
    const float* W2   = (const float*)d_in[3];   // [256,256]
    const float* b2   = (const float*)d_in[4];   // [256]
    const int*   esrc = (const int*)d_in[5];     // [320000]
    const int*   edst = (const int*)d_in[6];     // [320000]
    float*       out  = (float*)d_out;           // [10000,256]

    void *cat_p = nullptr, *h_p = nullptr, *w1_p = nullptr, *w2_p = nullptr;
    cudaGetSymbolAddress(&cat_p, g_cath);
    cudaGetSymbolAddress(&h_p, g_hh);
    cudaGetSymbolAddress(&w1_p, g_w1t);
    cudaGetSymbolAddress(&w2_p, g_w2t);
    const __half* cath = (const __half*)cat_p;
    __half*       hh   = (__half*)h_p;
    const __half* w1t  = (const __half*)w1_p;
    const __half* w2t  = (const __half*)w2_p;

    static bool attr_set = false;
    if (!attr_set) {
        cudaFuncSetAttribute(mma_gemm<0>,
                             cudaFuncAttributeMaxDynamicSharedMemorySize, SMEM_BYTES);
        cudaFuncSetAttribute(mma_gemm<1>,
                             cudaFuncAttributeMaxDynamicSharedMemorySize, SMEM_BYTES);
        attr_set = true;
    }

    // 1) prep: zero cursors, fp16 x, fp16 transposed weights
    prep_kernel<<<(N_NODES * H2 + 255) / 256, 256>>>(x, W1, W2);
    // 2) build padded adjacency
    fill_ell_kernel<<<(N_EDGES + 255) / 256, 256>>>(esrc, edst);
    // 3) gather + cat (fp16 gather, fp16 cat)
    gather_cat_kernel<<<(N_NODES * 32 + 255) / 256, 256>>>(x);
    // 4) h = cat @ W1 + b1  (fp16 mma + ldmatrix, 2-stage, 5 CTAs/SM)
    {
        dim3 grid((N_NODES + BM - 1) / BM, H2 / BN);
        mma_gemm<0><<<grid, 128, SMEM_BYTES>>>(cath, w1t, b1, hh, N_NODES, H2, H4);
    }
    // 5) out = tanh(h @ W2 + b2)
    {
        dim3 grid((N_NODES + BM - 1) / BM, H2 / BN);
        mma_gemm<1><<<grid, 128, SMEM_BYTES>>>(hh, w2t, b2, out, N_NODES, H2, H2);
    }
}

// round 17
// speedup vs baseline: 1.1265x; 1.0114x over previous
#include <cuda_runtime.h>
#include <cuda_fp16.h>
#include <math.h>
#include <stdint.h>

#define N_NODES 10000
#define N_EDGES 320000
#define H2 256          // node feature width
#define ELLW 128        // padded adjacency width

// Scratch (static __device__ arrays -- no allocation allowed)
__device__ int    g_ell[(size_t)N_NODES * ELLW];
__device__ int    g_cur[N_NODES];
__device__ __half g_xh[(size_t)N_NODES * H2];    // fp16 copy of x
__device__ __half g_pool[(size_t)N_NODES * H2];  // fp16 pooled = deg*x - S
__device__ float  g_hpart[(size_t)N_NODES * H2]; // fp32 partial h = x @ W1a
__device__ __half g_hh[(size_t)N_NODES * H2];    // fp16 h (GEMM1 output)
__device__ __half g_w1at[(size_t)H2 * H2];       // W1[0:256]^T  [n][k] fp16
__device__ __half g_w1bt[(size_t)H2 * H2];       // W1[256:512]^T [n][k] fp16
__device__ __half g_w2t[(size_t)H2 * H2];        // W2^T [n][k] fp16

// ---------------------------------------------------------------------------
// Prep: fp16 x copy + split transposed fp16 weights (stream 0)
// ---------------------------------------------------------------------------
__global__ void prep_kernel(const float* __restrict__ x,
                            const float* __restrict__ W1,
                            const float* __restrict__ W2) {
    int i = blockIdx.x * blockDim.x + threadIdx.x;
    if (i < N_NODES * H2) g_xh[i] = __float2half_rn(x[i]);
    if (i < H2 * H2) {
        int n = i >> 8, k = i & 255;
        g_w1at[(size_t)n * H2 + k] = __float2half_rn(W1[(size_t)k * H2 + n]);
        g_w1bt[(size_t)n * H2 + k] = __float2half_rn(W1[(size_t)(k + 256) * H2 + n]);
        g_w2t [(size_t)n * H2 + k] = __float2half_rn(W2[(size_t)k * H2 + n]);
    }
}

__global__ void zero_cur_kernel() {
    int idx = blockIdx.x * blockDim.x + threadIdx.x;
    if (idx < N_NODES) g_cur[idx] = 0;
}

__global__ void fill_ell_kernel(const int* __restrict__ esrc,
                                const int* __restrict__ edst) {
    int e = blockIdx.x * blockDim.x + threadIdx.x;
    if (e >= N_EDGES) return;
    int s = esrc[e];
    int d = edst[e];
    int pos = atomicAdd(&g_cur[d], 1);
    if (pos < ELLW) g_ell[((size_t)d << 7) + pos] = s;
}

// ---------------------------------------------------------------------------
// Gather -> pooled only (fp16). One warp per node; lane owns 8 cols.
// ---------------------------------------------------------------------------
union H8 { uint4 u; __half2 h[4]; };

__device__ __forceinline__ void acc8(float* a, uint4 v) {
    H8 p; p.u = v;
#pragma unroll
    for (int t = 0; t < 4; ++t) {
        float2 f = __half22float2(p.h[t]);
        a[2 * t]     += f.x;
        a[2 * t + 1] += f.y;
    }
}

__global__ __launch_bounds__(256)
void gather_kernel(const float* __restrict__ x) {
    int gtid = blockIdx.x * blockDim.x + threadIdx.x;
    int node = gtid >> 5;
    int lane = gtid & 31;
    if (node >= N_NODES) return;

    int deg = g_cur[node];
    const int* __restrict__ nbr = g_ell + ((size_t)node << 7);
    const uint4* __restrict__ xh4 = (const uint4*)g_xh;   // 32 chunks/row

    float a[8];
#pragma unroll
    for (int i = 0; i < 8; ++i) a[i] = 0.f;

    int j = 0;
    for (; j + 4 <= deg; j += 4) {
        int s0 = nbr[j], s1 = nbr[j + 1], s2 = nbr[j + 2], s3 = nbr[j + 3];
        uint4 v0 = xh4[(size_t)s0 * 32 + lane];
        uint4 v1 = xh4[(size_t)s1 * 32 + lane];
        uint4 v2 = xh4[(size_t)s2 * 32 + lane];
        uint4 v3 = xh4[(size_t)s3 * 32 + lane];
        acc8(a, v0); acc8(a, v1); acc8(a, v2); acc8(a, v3);
    }
    for (; j < deg; ++j) {
        uint4 v = xh4[(size_t)nbr[j] * 32 + lane];
        acc8(a, v);
    }

    const float4* x4 = (const float4*)x;
    float4 xa = x4[(size_t)node * 64 + 2 * lane];
    float4 xb = x4[(size_t)node * 64 + 2 * lane + 1];
    float dg = (float)deg;

    H8 po;
    po.h[0] = __floats2half2_rn(dg * xa.x - a[0], dg * xa.y - a[1]);
    po.h[1] = __floats2half2_rn(dg * xa.z - a[2], dg * xa.w - a[3]);
    po.h[2] = __floats2half2_rn(dg * xb.x - a[4], dg * xb.y - a[5]);
    po.h[3] = __floats2half2_rn(dg * xb.z - a[6], dg * xb.w - a[7]);

    ((uint4*)g_pool)[(size_t)node * 32 + lane] = po.u;
}

// ---------------------------------------------------------------------------
// fp16 mma.sync GEMM (m16n8k16, fp32 acc) + ldmatrix + 2-stage cp.async.
// Block 64x64x64, 128 threads (4 warps 2x2), warp tile 32x32. (R16-proven.)
// EPI: 2 = raw fp32 partial store (Gx)
//      0 = + aux(fp32 partial) + bias, fp16 store (G1b)
//      1 = + bias, tanh, fp32 store (G2)
// ---------------------------------------------------------------------------
__device__ __forceinline__ void cp16(uint32_t dst, const void* src, int srcsz) {
    asm volatile("cp.async.cg.shared.global [%0], [%1], 16, %2;"
                 :: "r"(dst), "l"(src), "r"(srcsz) : "memory");
}
#define CP_COMMIT() asm volatile("cp.async.commit_group;" ::: "memory")
#define CP_WAIT(n)  asm volatile("cp.async.wait_group %0;" :: "n"(n) : "memory")

#define LDSM_X4(r0, r1, r2, r3, addr) \
    asm volatile("ldmatrix.sync.aligned.m8n8.x4.shared.b16 {%0,%1,%2,%3}, [%4];" \
                 : "=r"(r0), "=r"(r1), "=r"(r2), "=r"(r3) : "r"(addr))

#define BM 64
#define BN 64
#define BK 64
#define LDK 72
#define A_ST (BM * LDK)
#define NSTAGE 2
#define SMEM_BYTES (2 * NSTAGE * A_ST * 2)   // 36864 B

template<int EPI>
__global__ __launch_bounds__(128, 5)
void mma_gemm(const __half* __restrict__ A, const __half* __restrict__ Bt,
              const float* __restrict__ bias, const float* __restrict__ aux,
              void* __restrict__ Cout, int M, int N, int K)
{
    extern __shared__ __half smh[];
    __half* Asm = smh;
    __half* Bsm = smh + NSTAGE * A_ST;
    uint32_t a_sa = (uint32_t)__cvta_generic_to_shared(Asm);
    uint32_t b_sa = (uint32_t)__cvta_generic_to_shared(Bsm);

    const int tid  = threadIdx.x;
    const int wid  = tid >> 5;
    const int lane = tid & 31;
    const int r = lane >> 2;
    const int c = lane & 3;
    const int wm0 = (wid & 1) * 32;
    const int wn0 = (wid >> 1) * 32;
    const int m0 = blockIdx.x * BM, n0 = blockIdx.y * BN;

    const int a_row = wm0 + (lane & 15);
    const int a_ksl = (lane >> 4) * 8;
    const int b_row = wn0 + (lane & 7) + ((lane >> 4) << 3);
    const int b_ksl = ((lane >> 3) & 1) * 8;

    float acc[2][4][4];
#pragma unroll
    for (int i = 0; i < 2; ++i)
#pragma unroll
        for (int j = 0; j < 4; ++j)
#pragma unroll
            for (int q = 0; q < 4; ++q) acc[i][j][q] = 0.f;

    const int T = K / BK;

    auto prefetch = [&](int t, int buf) {
        uint32_t ab = a_sa + (uint32_t)buf * A_ST * 2;
        uint32_t bb = b_sa + (uint32_t)buf * A_ST * 2;
        const __half* Ap = A + (size_t)t * BK;
        const __half* Bp = Bt + (size_t)t * BK;
#pragma unroll
        for (int i = 0; i < 4; ++i) {
            int ch  = tid + 128 * i;
            int row = ch >> 3, seg = ch & 7;
            int gm  = m0 + row;
            cp16(ab + row * (LDK * 2) + seg * 16,
                 Ap + (size_t)gm * K + seg * 8, gm < M ? 16 : 0);
            cp16(bb + row * (LDK * 2) + seg * 16,
                 Bp + (size_t)(n0 + row) * K + seg * 8, 16);
        }
        CP_COMMIT();
    };

    prefetch(0, 0);

    for (int t = 0; t < T; ++t) {
        int buf = t & 1;
        if (t + 1 < T) {
            prefetch(t + 1, 1 - buf);
            CP_WAIT(1);
        } else {
            CP_WAIT(0);
        }
        __syncthreads();

        uint32_t ab = a_sa + (uint32_t)buf * A_ST * 2;
        uint32_t bb = b_sa + (uint32_t)buf * A_ST * 2;

#pragma unroll
        for (int kt = 0; kt < 4; ++kt) {
            int kb = kt * 16;
            unsigned af[2][4], bf[2][4];
            LDSM_X4(af[0][0], af[0][1], af[0][2], af[0][3],
                    ab + (uint32_t)(a_row * LDK + kb + a_ksl) * 2);
            LDSM_X4(af[1][0], af[1][1], af[1][2], af[1][3],
                    ab + (uint32_t)((a_row + 16) * LDK + kb + a_ksl) * 2);
            LDSM_X4(bf[0][0], bf[0][1], bf[0][2], bf[0][3],
                    bb + (uint32_t)(b_row * LDK + kb + b_ksl) * 2);
            LDSM_X4(bf[1][0], bf[1][1], bf[1][2], bf[1][3],
                    bb + (uint32_t)((b_row + 16) * LDK + kb + b_ksl) * 2);
#pragma unroll
            for (int nt = 0; nt < 4; ++nt) {
                unsigned b0 = bf[nt >> 1][(nt & 1) * 2];
                unsigned b1 = bf[nt >> 1][(nt & 1) * 2 + 1];
#pragma unroll
                for (int mt = 0; mt < 2; ++mt) {
                    asm volatile(
                        "mma.sync.aligned.m16n8k16.row.col.f32.f16.f16.f32 "
                        "{%0,%1,%2,%3}, {%4,%5,%6,%7}, {%8,%9}, {%0,%1,%2,%3};"
                        : "+f"(acc[mt][nt][0]), "+f"(acc[mt][nt][1]),
                          "+f"(acc[mt][nt][2]), "+f"(acc[mt][nt][3])
                        : "r"(af[mt][0]), "r"(af[mt][1]),
                          "r"(af[mt][2]), "r"(af[mt][3]),
                          "r"(b0), "r"(b1));
                }
            }
        }
        __syncthreads();
    }

#pragma unroll
    for (int mt = 0; mt < 2; ++mt) {
#pragma unroll
        for (int half = 0; half < 2; ++half) {
            int gm = m0 + wm0 + mt * 16 + r + half * 8;
            if (gm >= M) continue;
#pragma unroll
            for (int nt = 0; nt < 4; ++nt) {
                int gn = n0 + wn0 + nt * 8 + 2 * c;
                float v0 = acc[mt][nt][half * 2 + 0];
                float v1 = acc[mt][nt][half * 2 + 1];
                if (EPI == 2) {
                    *(float2*)((float*)Cout + (size_t)gm * N + gn) =
                        make_float2(v0, v1);
                } else if (EPI == 0) {
                    float2 p = *(const float2*)(aux + (size_t)gm * N + gn);
                    v0 += p.x + bias[gn];
                    v1 += p.y + bias[gn + 1];
                    *(__half2*)((__half*)Cout + (size_t)gm * N + gn) =
                        __floats2half2_rn(v0, v1);
                } else {
                    v0 += bias[gn];
                    v1 += bias[gn + 1];
                    *(float2*)((float*)Cout + (size_t)gm * N + gn) =
                        make_float2(tanhf(v0), tanhf(v1));
                }
            }
        }
    }
}

// ---------------------------------------------------------------------------
extern "C" void kernel_launch(void* const* d_in, const int* in_sizes, int n_in,
                              void* d_out, int out_size) {
    const float* x    = (const float*)d_in[0];
    const float* W1   = (const float*)d_in[1];
    const float* b1   = (const float*)d_in[2];
    const float* W2   = (const float*)d_in[3];
    const float* b2   = (const float*)d_in[4];
    const int*   esrc = (const int*)d_in[5];
    const int*   edst = (const int*)d_in[6];
    float*       out  = (float*)d_out;

    void *xh_p, *pool_p, *hpart_p, *hh_p, *w1a_p, *w1b_p, *w2_p;
    cudaGetSymbolAddress(&xh_p, g_xh);
    cudaGetSymbolAddress(&pool_p, g_pool);
    cudaGetSymbolAddress(&hpart_p, g_hpart);
    cudaGetSymbolAddress(&hh_p, g_hh);
    cudaGetSymbolAddress(&w1a_p, g_w1at);
    cudaGetSymbolAddress(&w1b_p, g_w1bt);
    cudaGetSymbolAddress(&w2_p, g_w2t);
    const __half* xh   = (const __half*)xh_p;
    const __half* pool = (const __half*)pool_p;
    float*        hp   = (float*)hpart_p;
    __half*       hh   = (__half*)hh_p;
    const __half* w1at = (const __half*)w1a_p;
    const __half* w1bt = (const __half*)w1b_p;
    const __half* w2t  = (const __half*)w2_p;

    static cudaStream_t s1;
    static cudaEvent_t evRoot, evPrep, evGather;
    static bool inited = false;
    if (!inited) {
        cudaStreamCreateWithFlags(&s1, cudaStreamNonBlocking);
        cudaEventCreateWithFlags(&evRoot, cudaEventDisableTiming);
        cudaEventCreateWithFlags(&evPrep, cudaEventDisableTiming);
        cudaEventCreateWithFlags(&evGather, cudaEventDisableTiming);
        cudaFuncSetAttribute(mma_gemm<0>,
            cudaFuncAttributeMaxDynamicSharedMemorySize, SMEM_BYTES);
        cudaFuncSetAttribute(mma_gemm<1>,
            cudaFuncAttributeMaxDynamicSharedMemorySize, SMEM_BYTES);
        cudaFuncSetAttribute(mma_gemm<2>,
            cudaFuncAttributeMaxDynamicSharedMemorySize, SMEM_BYTES);
        inited = true;
    }

    dim3 ggrid((N_NODES + BM - 1) / BM, H2 / BN);   // 157 x 4

    // ---- fork: s1 = graph-build branch, stream 0 = dense branch ----
    cudaEventRecord(evRoot, 0);
    cudaStreamWaitEvent(s1, evRoot, 0);

    // s1: zero cursors -> fill adjacency
    zero_cur_kernel<<<(N_NODES + 255) / 256, 256, 0, s1>>>();
    fill_ell_kernel<<<(N_EDGES + 255) / 256, 256, 0, s1>>>(esrc, edst);

    // stream 0: prep (xh + weights)
    prep_kernel<<<(N_NODES * H2 + 255) / 256, 256>>>(x, W1, W2);
    cudaEventRecord(evPrep, 0);
    cudaStreamWaitEvent(s1, evPrep, 0);

    // stream 0: Gx = x @ W1a -> fp32 partial   (overlaps gather on s1)
    mma_gemm<2><<<ggrid, 128, SMEM_BYTES>>>(
        xh, w1at, nullptr, nullptr, hp, N_NODES, H2, H2);

    // s1: gather -> pooled (needs prep's xh + fill's adjacency)
    gather_kernel<<<(N_NODES * 32 + 255) / 256, 256, 0, s1>>>(x);
    cudaEventRecord(evGather, s1);
    cudaStreamWaitEvent(0, evGather, 0);

    // stream 0: h = pooled @ W1b + hpart + b1 -> fp16
    mma_gemm<0><<<ggrid, 128, SMEM_BYTES>>>(
        pool, w1bt, b1, hp, hh, N_NODES, H2, H2);

    // stream 0: out = tanh(h @ W2 + b2)
    mma_gemm<1><<<ggrid, 128, SMEM_BYTES>>>(
        hh, w2t, b2, nullptr, out, N_NODES, H2, H2);
}